// round 2
// baseline (speedup 1.0000x reference)
#include <cuda_runtime.h>

// ---------------------------------------------------------------------------
// Attention3D: x(2,8,16,16,768) -> qkv -> 12-head attention with decomposed
// rel-pos bias -> proj.  B*nh = 24 head-batches, N = 2048 tokens, hd = 64.
// All fp32.  4 kernels: qkv gemm (scatter epilogue), rel-pos precompute,
// fused flash attention (online softmax, bias on the fly), proj gemm.
// ---------------------------------------------------------------------------

#define NHB   24      // B * num_heads
#define NSEQ  2048    // D*H*W
#define HD    64
#define CDIM  768
#define MROWS 4096    // B * N

// Scratch (no cudaMalloc allowed) -------------------------------------------
__device__ float g_q[NHB * NSEQ * HD];
__device__ float g_k[NHB * NSEQ * HD];
__device__ float g_v[NHB * NSEQ * HD];
__device__ float g_reld[NHB * NSEQ * 8];
__device__ float g_relh[NHB * NSEQ * 16];
__device__ float g_relw[NHB * NSEQ * 16];
__device__ float g_attnout[MROWS * CDIM];

// ---------------------------------------------------------------------------
// QKV GEMM:  (4096 x 768) @ (768 x 2304) + bias, scattered to g_q/g_k/g_v
// laid out as [hb][n][c]  (hb = b*12 + head).
// Tiling: 64x64 block, K-step 16, 256 threads, 4x4 micro-tile.
// ---------------------------------------------------------------------------
__global__ void __launch_bounds__(256) qkv_gemm_kernel(
    const float* __restrict__ x, const float* __restrict__ w,
    const float* __restrict__ bias)
{
    __shared__ float As[16][64];   // A transposed: As[k][m]
    __shared__ float Bs[16][64];   // Bs[k][n]
    const int bm = blockIdx.x * 64;
    const int bn = blockIdx.y * 64;
    const int tid = threadIdx.x;
    const int tx = tid & 15, ty = tid >> 4;
    const int ka = tid & 15, ma = (tid >> 4) << 2;
    const int nb = tid & 63, kb = tid >> 6;
    float acc[4][4] = {};

    for (int k0 = 0; k0 < 768; k0 += 16) {
#pragma unroll
        for (int i = 0; i < 4; i++)
            As[ka][ma + i] = x[(bm + ma + i) * 768 + k0 + ka];
#pragma unroll
        for (int i = 0; i < 4; i++)
            Bs[kb + i * 4][nb] = w[(k0 + kb + i * 4) * 2304 + bn + nb];
        __syncthreads();
#pragma unroll
        for (int kk = 0; kk < 16; kk++) {
            float4 a4 = *(const float4*)&As[kk][ty << 2];
            float4 b4 = *(const float4*)&Bs[kk][tx << 2];
            float av[4] = {a4.x, a4.y, a4.z, a4.w};
            float bv[4] = {b4.x, b4.y, b4.z, b4.w};
#pragma unroll
            for (int ii = 0; ii < 4; ii++)
#pragma unroll
                for (int jj = 0; jj < 4; jj++)
                    acc[ii][jj] += av[ii] * bv[jj];
        }
        __syncthreads();
    }

#pragma unroll
    for (int ii = 0; ii < 4; ii++) {
        const int mrow = bm + (ty << 2) + ii;
        const int b = mrow >> 11, n = mrow & 2047;
#pragma unroll
        for (int jj = 0; jj < 4; jj++) {
            const int j = bn + (tx << 2) + jj;
            const float val = acc[ii][jj] + bias[j];
            const int which = j / 768;
            const int head = (j % 768) >> 6;
            const int c = j & 63;
            float* dst = (which == 0) ? g_q : (which == 1) ? g_k : g_v;
            dst[((b * 12 + head) * NSEQ + n) * HD + c] = val;
        }
    }
}

// ---------------------------------------------------------------------------
// Rel-pos bias tables: rel_d[hb][n][kd] = q[hb][n] . rel_pos_d[d(n)-kd+7]
// (and likewise h with +15, w with +15).  One thread per output scalar.
// ---------------------------------------------------------------------------
__global__ void __launch_bounds__(256) relpos_kernel(
    const float* __restrict__ rpd, const float* __restrict__ rph,
    const float* __restrict__ rpw)
{
    const int idx = blockIdx.x * 256 + threadIdx.x;   // NHB*NSEQ*40 total
    if (idx >= NHB * NSEQ * 40) return;
    const int j  = idx % 40;
    const int n  = (idx / 40) % NSEQ;
    const int hb = idx / (40 * NSEQ);
    const float* qrow = &g_q[(hb * NSEQ + n) * HD];
    const int d = n >> 8, h = (n >> 4) & 15, wq = n & 15;

    const float* trow;
    float* dst;
    if (j < 8) {
        trow = &rpd[(d - j + 7) * HD];
        dst  = &g_reld[(hb * NSEQ + n) * 8 + j];
    } else if (j < 24) {
        const int kh = j - 8;
        trow = &rph[(h - kh + 15) * HD];
        dst  = &g_relh[(hb * NSEQ + n) * 16 + kh];
    } else {
        const int kw = j - 24;
        trow = &rpw[(wq - kw + 15) * HD];
        dst  = &g_relw[(hb * NSEQ + n) * 16 + kw];
    }
    float s = 0.f;
#pragma unroll
    for (int c = 0; c < HD; c++) s += qrow[c] * trow[c];
    *dst = s;
}

// ---------------------------------------------------------------------------
// Fused flash attention with decomposed bias.
// Block = (q-tile of 64, head-batch).  256 threads (16x16), 4x4 micro-tiles.
// Dynamic smem layout (floats):
//   Qt [64][68]  (c-major, padded)   @ 0      (4352)
//   Kt [64][68]                      @ 4352   (4352)
//   Vs [64][64]  (k-major)           @ 8704   (4096)
//   Ps [64][64]  (q-major)           @ 12800  (4096)
//   rD [64][8]                       @ 16896  (512)
//   rH [64][16]                      @ 17408  (1024)
//   rW [64][16]                      @ 18432  (1024)   total 19456 fl = 77824 B
// ---------------------------------------------------------------------------
#define FL_SMEM_FLOATS 19456
#define FL_SMEM_BYTES  (FL_SMEM_FLOATS * 4)

__global__ void __launch_bounds__(256) flash_kernel()
{
    extern __shared__ float sm[];
    float* Qt = sm;
    float* Kt = sm + 4352;
    float* Vs = sm + 8704;
    float* Ps = sm + 12800;
    float* rD = sm + 16896;
    float* rH = sm + 17408;
    float* rW = sm + 18432;

    const int qt = blockIdx.x;          // 0..31
    const int hb = blockIdx.y;          // 0..23
    const int tid = threadIdx.x;
    const int tx = tid & 15, ty = tid >> 4;
    const int qbase = qt * 64;
    const float scale = 0.125f;         // hd^-0.5

    // --- load Q tile transposed (pitch 68) ---
    const float* Qg = &g_q[(hb * NSEQ + qbase) * HD];
#pragma unroll
    for (int it = 0; it < 4; it++) {
        const int f = it * 1024 + tid * 4;
        const int r = f >> 6, c0 = f & 63;
        float4 v = *(const float4*)&Qg[f];
        Qt[(c0 + 0) * 68 + r] = v.x;
        Qt[(c0 + 1) * 68 + r] = v.y;
        Qt[(c0 + 2) * 68 + r] = v.z;
        Qt[(c0 + 3) * 68 + r] = v.w;
    }
    // --- rel bias tables for these 64 queries (contiguous in global) ---
    for (int i = tid; i < 64 * 8; i += 256)
        rD[i] = g_reld[(hb * NSEQ + qbase) * 8 + i];
    for (int i = tid; i < 64 * 16; i += 256)
        rH[i] = g_relh[(hb * NSEQ + qbase) * 16 + i];
    for (int i = tid; i < 64 * 16; i += 256)
        rW[i] = g_relw[(hb * NSEQ + qbase) * 16 + i];

    float m[4], l[4], o[4][4];
#pragma unroll
    for (int ii = 0; ii < 4; ii++) {
        m[ii] = -1e30f; l[ii] = 0.f;
#pragma unroll
        for (int jj = 0; jj < 4; jj++) o[ii][jj] = 0.f;
    }

    for (int kt = 0; kt < 32; kt++) {
        __syncthreads();   // Q/rel ready (kt=0); prev O-update done with Ps/Vs
        const float* Kg = &g_k[(hb * NSEQ + kt * 64) * HD];
        const float* Vg = &g_v[(hb * NSEQ + kt * 64) * HD];
#pragma unroll
        for (int it = 0; it < 4; it++) {
            const int f = it * 1024 + tid * 4;
            const int r = f >> 6, c0 = f & 63;
            float4 kv = *(const float4*)&Kg[f];
            Kt[(c0 + 0) * 68 + r] = kv.x;
            Kt[(c0 + 1) * 68 + r] = kv.y;
            Kt[(c0 + 2) * 68 + r] = kv.z;
            Kt[(c0 + 3) * 68 + r] = kv.w;
            *(float4*)&Vs[f] = *(const float4*)&Vg[f];
        }
        __syncthreads();

        // --- S = Q K^T (64x64 over c=64) ---
        float s[4][4] = {};
#pragma unroll 8
        for (int c = 0; c < 64; c++) {
            float4 a4 = *(const float4*)&Qt[c * 68 + (ty << 2)];
            float4 b4 = *(const float4*)&Kt[c * 68 + (tx << 2)];
            float av[4] = {a4.x, a4.y, a4.z, a4.w};
            float bv[4] = {b4.x, b4.y, b4.z, b4.w};
#pragma unroll
            for (int ii = 0; ii < 4; ii++)
#pragma unroll
                for (int jj = 0; jj < 4; jj++)
                    s[ii][jj] += av[ii] * bv[jj];
        }

        // --- scale + decomposed rel-pos bias ---
        const int kd = kt >> 2;   // constant within a 64-key tile
#pragma unroll
        for (int ii = 0; ii < 4; ii++) {
            const int qr = (ty << 2) + ii;
            const float bd = rD[qr * 8 + kd];
#pragma unroll
            for (int jj = 0; jj < 4; jj++) {
                const int off = (tx << 2) + jj;
                const int kg = (kt << 6) + off;
                const int kh = (kg >> 4) & 15;
                const int kw = kg & 15;
                s[ii][jj] = s[ii][jj] * scale + bd + rH[qr * 16 + kh] + rW[qr * 16 + kw];
            }
        }

        // --- online softmax (row groups of 16 lanes share a q-row) ---
#pragma unroll
        for (int ii = 0; ii < 4; ii++) {
            float rmax = fmaxf(fmaxf(s[ii][0], s[ii][1]), fmaxf(s[ii][2], s[ii][3]));
#pragma unroll
            for (int off = 8; off >= 1; off >>= 1)
                rmax = fmaxf(rmax, __shfl_xor_sync(0xffffffffu, rmax, off));
            const float mn = fmaxf(m[ii], rmax);
            const float corr = __expf(m[ii] - mn);
            m[ii] = mn;
            float rs = 0.f;
#pragma unroll
            for (int jj = 0; jj < 4; jj++) {
                s[ii][jj] = __expf(s[ii][jj] - mn);
                rs += s[ii][jj];
            }
#pragma unroll
            for (int off = 8; off >= 1; off >>= 1)
                rs += __shfl_xor_sync(0xffffffffu, rs, off);
            l[ii] = l[ii] * corr + rs;
#pragma unroll
            for (int jj = 0; jj < 4; jj++) o[ii][jj] *= corr;
            *(float4*)&Ps[((ty << 2) + ii) * 64 + (tx << 2)] =
                make_float4(s[ii][0], s[ii][1], s[ii][2], s[ii][3]);
        }
        __syncthreads();

        // --- O += P V ---
#pragma unroll 4
        for (int k = 0; k < 64; k++) {
            float4 vv = *(const float4*)&Vs[k * 64 + (tx << 2)];
#pragma unroll
            for (int ii = 0; ii < 4; ii++) {
                const float p = Ps[((ty << 2) + ii) * 64 + k];
                o[ii][0] += p * vv.x;
                o[ii][1] += p * vv.y;
                o[ii][2] += p * vv.z;
                o[ii][3] += p * vv.w;
            }
        }
    }

    // --- finalize: O /= l, write interleaved (B,N, head*64+c) for proj ---
    const int b = hb / 12, head = hb % 12;
#pragma unroll
    for (int ii = 0; ii < 4; ii++) {
        const float inv = 1.0f / l[ii];
        const int qg = qbase + (ty << 2) + ii;
        float4 ov = make_float4(o[ii][0] * inv, o[ii][1] * inv,
                                o[ii][2] * inv, o[ii][3] * inv);
        *(float4*)&g_attnout[(b * NSEQ + qg) * CDIM + head * 64 + (tx << 2)] = ov;
    }
}

// ---------------------------------------------------------------------------
// Proj GEMM: (4096 x 768) @ (768 x 768) + bias -> d_out (row-major, matches
// (B,D,H,W,C)).
// ---------------------------------------------------------------------------
__global__ void __launch_bounds__(256) proj_gemm_kernel(
    const float* __restrict__ w, const float* __restrict__ bias,
    float* __restrict__ out)
{
    __shared__ float As[16][64];
    __shared__ float Bs[16][64];
    const int bm = blockIdx.x * 64;
    const int bn = blockIdx.y * 64;
    const int tid = threadIdx.x;
    const int tx = tid & 15, ty = tid >> 4;
    const int ka = tid & 15, ma = (tid >> 4) << 2;
    const int nb = tid & 63, kb = tid >> 6;
    float acc[4][4] = {};

    for (int k0 = 0; k0 < 768; k0 += 16) {
#pragma unroll
        for (int i = 0; i < 4; i++)
            As[ka][ma + i] = g_attnout[(bm + ma + i) * 768 + k0 + ka];
#pragma unroll
        for (int i = 0; i < 4; i++)
            Bs[kb + i * 4][nb] = w[(k0 + kb + i * 4) * 768 + bn + nb];
        __syncthreads();
#pragma unroll
        for (int kk = 0; kk < 16; kk++) {
            float4 a4 = *(const float4*)&As[kk][ty << 2];
            float4 b4 = *(const float4*)&Bs[kk][tx << 2];
            float av[4] = {a4.x, a4.y, a4.z, a4.w};
            float bv[4] = {b4.x, b4.y, b4.z, b4.w};
#pragma unroll
            for (int ii = 0; ii < 4; ii++)
#pragma unroll
                for (int jj = 0; jj < 4; jj++)
                    acc[ii][jj] += av[ii] * bv[jj];
        }
        __syncthreads();
    }

#pragma unroll
    for (int ii = 0; ii < 4; ii++) {
        const int mrow = bm + (ty << 2) + ii;
#pragma unroll
        for (int jj = 0; jj < 4; jj++) {
            const int j = bn + (tx << 2) + jj;
            out[mrow * 768 + j] = acc[ii][jj] + bias[j];
        }
    }
}

// ---------------------------------------------------------------------------
extern "C" void kernel_launch(void* const* d_in, const int* in_sizes, int n_in,
                              void* d_out, int out_size)
{
    const float* x      = (const float*)d_in[0];
    const float* qkv_w  = (const float*)d_in[1];
    const float* qkv_b  = (const float*)d_in[2];
    const float* proj_w = (const float*)d_in[3];
    const float* proj_b = (const float*)d_in[4];
    const float* rpd    = (const float*)d_in[5];
    const float* rph    = (const float*)d_in[6];
    const float* rpw    = (const float*)d_in[7];
    float* out = (float*)d_out;

    cudaFuncSetAttribute(flash_kernel,
                         cudaFuncAttributeMaxDynamicSharedMemorySize,
                         FL_SMEM_BYTES);

    qkv_gemm_kernel<<<dim3(64, 36), 256>>>(x, qkv_w, qkv_b);
    relpos_kernel<<<(NHB * NSEQ * 40 + 255) / 256, 256>>>(rpd, rph, rpw);
    flash_kernel<<<dim3(32, NHB), 256, FL_SMEM_BYTES>>>();
    proj_gemm_kernel<<<dim3(64, 12), 256>>>(proj_w, proj_b, out);
}

// round 3
// speedup vs baseline: 2.1353x; 2.1353x over previous
#include <cuda_runtime.h>
#include <stdint.h>

// ---------------------------------------------------------------------------
// Attention3D on tf32 tensor cores (mma.sync m16n8k8).
//   1) QKV GEMM 4096x2304x768 -> scatter to Q/K (natural) and V (transposed)
//   2) rel-pos tables (SIMT, tiny)
//   3) flash attention Br=128 Bc=64, tf32 mma + fp32 online softmax,
//      decomposed rel-pos bias folded per logit
//   4) proj GEMM 4096x768x768 -> d_out
// ---------------------------------------------------------------------------

#define NHB  24
#define NSEQ 2048
#define HD   64
#define CDIM 768

__device__ float g_q[NHB * NSEQ * HD];
__device__ float g_k[NHB * NSEQ * HD];
__device__ float g_v[NHB * HD * NSEQ];       // TRANSPOSED: [hb][c][key]
__device__ float g_reld[NHB * NSEQ * 8];
__device__ float g_relh[NHB * NSEQ * 16];
__device__ float g_relw[NHB * NSEQ * 16];
__device__ float g_attnout[4096 * CDIM];

__device__ __forceinline__ uint32_t f2tf32(float x) {
    uint32_t u;
    asm("cvt.rna.tf32.f32 %0, %1;" : "=r"(u) : "f"(x));
    return u;
}

__device__ __forceinline__ void ldsm4(uint32_t r[4], const float* p) {
    uint32_t a = (uint32_t)__cvta_generic_to_shared(p);
    asm volatile("ldmatrix.sync.aligned.m8n8.x4.shared.b16 {%0,%1,%2,%3}, [%4];"
                 : "=r"(r[0]), "=r"(r[1]), "=r"(r[2]), "=r"(r[3]) : "r"(a));
}

__device__ __forceinline__ void mma8(float d[4], const uint32_t a[4],
                                     uint32_t b0, uint32_t b1) {
    asm volatile(
        "mma.sync.aligned.m16n8k8.row.col.f32.tf32.tf32.f32 "
        "{%0,%1,%2,%3}, {%4,%5,%6,%7}, {%8,%9}, {%0,%1,%2,%3};"
        : "+f"(d[0]), "+f"(d[1]), "+f"(d[2]), "+f"(d[3])
        : "r"(a[0]), "r"(a[1]), "r"(a[2]), "r"(a[3]), "r"(b0), "r"(b1));
}

// ---------------------------------------------------------------------------
// tf32 GEMM: C[4096 x N] = A @ W + bias.  MODE 0: N=2304 scatter to q/k/v.
// MODE 1: N=768 -> out.  Tile 128x128 k16, 8 warps 4m x 2n, warp 32x64.
// ---------------------------------------------------------------------------
template <int MODE>
__global__ void __launch_bounds__(256) mm_tf32(
    const float* __restrict__ A_, const float* __restrict__ W,
    const float* __restrict__ bias, float* __restrict__ out)
{
    constexpr int N = (MODE == 0) ? 2304 : 768;
    __shared__ float As[128 * 20];   // [m][k] pitch 20 (ldmatrix, conflict-free)
    __shared__ float Bs[16 * 136];   // [k][n] pitch 136 (scalar frags, cf)
    const int tid = threadIdx.x, lane = tid & 31, w = tid >> 5;
    const int wm = w >> 1, wn = w & 1;
    const int bm = blockIdx.x * 128, bn = blockIdx.y * 128;
    const float* Ap = (MODE == 0) ? A_ : g_attnout;

    float c[2][8][4];
#pragma unroll
    for (int i = 0; i < 2; i++)
#pragma unroll
        for (int j = 0; j < 8; j++)
#pragma unroll
            for (int k = 0; k < 4; k++) c[i][j][k] = 0.f;

    for (int k0 = 0; k0 < 768; k0 += 16) {
        __syncthreads();
#pragma unroll
        for (int it = 0; it < 2; it++) {
            const int i = tid + it * 256;            // 512 float4s of A
            const int r = i >> 2, c4 = (i & 3) << 2;
            float4 v = *(const float4*)&Ap[(bm + r) * 768 + k0 + c4];
            uint32_t* d = (uint32_t*)&As[r * 20 + c4];
            d[0] = f2tf32(v.x); d[1] = f2tf32(v.y);
            d[2] = f2tf32(v.z); d[3] = f2tf32(v.w);
        }
#pragma unroll
        for (int it = 0; it < 2; it++) {
            const int i = tid + it * 256;            // 512 float4s of W
            const int kk = i >> 5, n4 = (i & 31) << 2;
            float4 v = *(const float4*)&W[(k0 + kk) * N + bn + n4];
            uint32_t* d = (uint32_t*)&Bs[kk * 136 + n4];
            d[0] = f2tf32(v.x); d[1] = f2tf32(v.y);
            d[2] = f2tf32(v.z); d[3] = f2tf32(v.w);
        }
        __syncthreads();

        const uint32_t* bp = (const uint32_t*)Bs;
#pragma unroll
        for (int ks = 0; ks < 2; ks++) {
            uint32_t a0[4], a1[4];
            ldsm4(a0, &As[(wm * 32 + ((lane >> 3) & 1) * 8 + (lane & 7)) * 20
                          + ks * 8 + (lane >> 4) * 4]);
            ldsm4(a1, &As[(wm * 32 + 16 + ((lane >> 3) & 1) * 8 + (lane & 7)) * 20
                          + ks * 8 + (lane >> 4) * 4]);
#pragma unroll
            for (int nt = 0; nt < 8; nt++) {
                const int ncol = wn * 64 + nt * 8 + (lane >> 2);
                uint32_t b0 = bp[(ks * 8 + (lane & 3)) * 136 + ncol];
                uint32_t b1 = bp[(ks * 8 + 4 + (lane & 3)) * 136 + ncol];
                mma8(c[0][nt], a0, b0, b1);
                mma8(c[1][nt], a1, b0, b1);
            }
        }
    }

    if (MODE == 0) {
        const int hc = bn + wn * 64;                 // 64-aligned
        const int which = hc / 768;
        const int head = (hc % 768) >> 6;
#pragma unroll
        for (int mt = 0; mt < 2; mt++)
#pragma unroll
            for (int nt = 0; nt < 8; nt++) {
                const int ccol = nt * 8 + ((lane & 3) << 1);
                const float b0v = bias[hc + ccol];
                const float b1v = bias[hc + ccol + 1];
#pragma unroll
                for (int h = 0; h < 2; h++) {
                    const int row = bm + wm * 32 + mt * 16 + (lane >> 2) + 8 * h;
                    const int b_ = row >> 11, n = row & 2047;
                    const int hb = b_ * 12 + head;
                    const float v0 = c[mt][nt][2 * h] + b0v;
                    const float v1 = c[mt][nt][2 * h + 1] + b1v;
                    if (which == 0)
                        *(float2*)&g_q[((hb * NSEQ + n) << 6) + ccol] = make_float2(v0, v1);
                    else if (which == 1)
                        *(float2*)&g_k[((hb * NSEQ + n) << 6) + ccol] = make_float2(v0, v1);
                    else {
                        g_v[hb * (HD * NSEQ) + ccol * NSEQ + n] = v0;
                        g_v[hb * (HD * NSEQ) + (ccol + 1) * NSEQ + n] = v1;
                    }
                }
            }
    } else {
#pragma unroll
        for (int mt = 0; mt < 2; mt++)
#pragma unroll
            for (int nt = 0; nt < 8; nt++) {
                const int col = bn + wn * 64 + nt * 8 + ((lane & 3) << 1);
                const float b0v = bias[col], b1v = bias[col + 1];
#pragma unroll
                for (int h = 0; h < 2; h++) {
                    const int row = bm + wm * 32 + mt * 16 + (lane >> 2) + 8 * h;
                    *(float2*)&out[row * 768 + col] =
                        make_float2(c[mt][nt][2 * h] + b0v, c[mt][nt][2 * h + 1] + b1v);
                }
            }
    }
}

// ---------------------------------------------------------------------------
// Rel-pos tables (fp32 SIMT, tiny)
// ---------------------------------------------------------------------------
__global__ void __launch_bounds__(256) relpos_kernel(
    const float* __restrict__ rpd, const float* __restrict__ rph,
    const float* __restrict__ rpw)
{
    const int idx = blockIdx.x * 256 + threadIdx.x;
    if (idx >= NHB * NSEQ * 40) return;
    const int j = idx % 40;
    const int n = (idx / 40) % NSEQ;
    const int hb = idx / (40 * NSEQ);
    const float* qrow = &g_q[(hb * NSEQ + n) * HD];
    const int d = n >> 8, h = (n >> 4) & 15, wq = n & 15;
    const float* trow;
    float* dst;
    if (j < 8)       { trow = &rpd[(d - j + 7) * HD];        dst = &g_reld[(hb * NSEQ + n) * 8 + j]; }
    else if (j < 24) { const int kh = j - 8;  trow = &rph[(h - kh + 15) * HD];  dst = &g_relh[(hb * NSEQ + n) * 16 + kh]; }
    else             { const int kw = j - 24; trow = &rpw[(wq - kw + 15) * HD]; dst = &g_relw[(hb * NSEQ + n) * 16 + kw]; }
    float s = 0.f;
#pragma unroll
    for (int c = 0; c < HD; c++) s += qrow[c] * trow[c];
    *dst = s;
}

// ---------------------------------------------------------------------------
// Flash attention, tf32 mma.  Grid (16 q-tiles of 128, 24 hb).  256 threads,
// 8 warps; warp w owns q rows [w*16, w*16+16).
// smem (floats): Qs 128x68, Ks 64x68, Vt 64x68 (c-major), Ps 128x68,
//                rDt 8x128, rHt 16x128, rWt 16x128.
// ---------------------------------------------------------------------------
#define QS_OFF 0
#define KS_OFF 8704
#define VT_OFF 13056
#define PS_OFF 17408
#define RD_OFF 26112
#define RH_OFF 27136
#define RW_OFF 29184
#define FL_FLOATS 31232
#define FL_BYTES  (FL_FLOATS * 4)

__global__ void __launch_bounds__(256, 1) flash_kernel()
{
    extern __shared__ float sm[];
    float* Qs  = sm + QS_OFF;
    float* Ks  = sm + KS_OFF;
    float* Vt  = sm + VT_OFF;
    float* Ps  = sm + PS_OFF;
    float* rDt = sm + RD_OFF;
    float* rHt = sm + RH_OFF;
    float* rWt = sm + RW_OFF;

    const int tid = threadIdx.x, lane = tid & 31, w = tid >> 5;
    const int hb = blockIdx.y;
    const int qbase = blockIdx.x * 128;
    const float scale = 0.125f;

    // --- stage Q (tf32) + bias tables ---
    const float* Qg = &g_q[(hb * NSEQ + qbase) * HD];
#pragma unroll
    for (int it = 0; it < 8; it++) {
        const int f = it * 1024 + tid * 4;          // 128*64 floats
        const int r = f >> 6, c0 = f & 63;
        float4 v = *(const float4*)&Qg[f];
        uint32_t* d = (uint32_t*)&Qs[r * 68 + c0];
        d[0] = f2tf32(v.x); d[1] = f2tf32(v.y);
        d[2] = f2tf32(v.z); d[3] = f2tf32(v.w);
    }
    for (int i = tid; i < 128 * 8; i += 256)
        rDt[(i & 7) * 128 + (i >> 3)] = g_reld[(hb * NSEQ + qbase + (i >> 3)) * 8 + (i & 7)];
    for (int i = tid; i < 128 * 16; i += 256)
        rHt[(i & 15) * 128 + (i >> 4)] = g_relh[(hb * NSEQ + qbase + (i >> 4)) * 16 + (i & 15)];
    for (int i = tid; i < 128 * 16; i += 256)
        rWt[(i & 15) * 128 + (i >> 4)] = g_relw[(hb * NSEQ + qbase + (i >> 4)) * 16 + (i & 15)];
    __syncthreads();

    // --- hoist Q A-fragments (16 rows x 64 c per warp) ---
    uint32_t aq[8][4];
#pragma unroll
    for (int ks = 0; ks < 8; ks++)
        ldsm4(aq[ks], &Qs[(w * 16 + ((lane >> 3) & 1) * 8 + (lane & 7)) * 68
                          + ks * 8 + (lane >> 4) * 4]);
    // row indices + hoisted rW values
    int rq[2];
    rq[0] = w * 16 + (lane >> 2);
    rq[1] = rq[0] + 8;
    float rw[2][2][2];
#pragma unroll
    for (int p = 0; p < 2; p++)
#pragma unroll
        for (int j2 = 0; j2 < 2; j2++)
#pragma unroll
            for (int h = 0; h < 2; h++)
                rw[p][j2][h] = rWt[(8 * p + 2 * (lane & 3) + j2) * 128 + rq[h]];

    float m[2] = {-1e30f, -1e30f}, l[2] = {0.f, 0.f};
    float o[8][4];
#pragma unroll
    for (int i = 0; i < 8; i++)
#pragma unroll
        for (int j = 0; j < 4; j++) o[i][j] = 0.f;

    for (int kt = 0; kt < 32; kt++) {
        __syncthreads();
        // stage K (natural [key][c]) and V (already transposed in global)
        const float* Kg = &g_k[(hb * NSEQ + kt * 64) * HD];
        const float* Vg = &g_v[hb * (HD * NSEQ) + kt * 64];
#pragma unroll
        for (int it = 0; it < 4; it++) {
            const int f = it * 1024 + tid * 4;      // 64*64
            const int r = f >> 6, c0 = f & 63;
            float4 kv = *(const float4*)&Kg[f];
            uint32_t* dk = (uint32_t*)&Ks[r * 68 + c0];
            dk[0] = f2tf32(kv.x); dk[1] = f2tf32(kv.y);
            dk[2] = f2tf32(kv.z); dk[3] = f2tf32(kv.w);
            float4 vv = *(const float4*)&Vg[r * NSEQ + c0];   // r=c row, c0=key
            uint32_t* dv = (uint32_t*)&Vt[r * 68 + c0];
            dv[0] = f2tf32(vv.x); dv[1] = f2tf32(vv.y);
            dv[2] = f2tf32(vv.z); dv[3] = f2tf32(vv.w);
        }
        __syncthreads();

        // --- S = Q K^T ---
        float s[8][4];
#pragma unroll
        for (int i = 0; i < 8; i++)
#pragma unroll
            for (int j = 0; j < 4; j++) s[i][j] = 0.f;
#pragma unroll
        for (int ksp = 0; ksp < 4; ksp++) {
#pragma unroll
            for (int nt = 0; nt < 8; nt++) {
                uint32_t k4[4];
                ldsm4(k4, &Ks[(nt * 8 + (lane & 7)) * 68 + ksp * 16 + (lane >> 3) * 4]);
                mma8(s[nt], aq[2 * ksp], k4[0], k4[1]);
                mma8(s[nt], aq[2 * ksp + 1], k4[2], k4[3]);
            }
        }

        // --- bias ---
        const int kd = kt >> 2;
        float bh[4][2];
#pragma unroll
        for (int g = 0; g < 4; g++)
#pragma unroll
            for (int h = 0; h < 2; h++)
                bh[g][h] = rDt[kd * 128 + rq[h]]
                         + rHt[((kt & 3) * 4 + g) * 128 + rq[h]];
#pragma unroll
        for (int nt = 0; nt < 8; nt++)
#pragma unroll
            for (int h = 0; h < 2; h++)
#pragma unroll
                for (int j2 = 0; j2 < 2; j2++)
                    s[nt][2 * h + j2] = fmaf(s[nt][2 * h + j2], scale,
                                             bh[nt >> 1][h] + rw[nt & 1][j2][h]);

        // --- online softmax per row half ---
#pragma unroll
        for (int h = 0; h < 2; h++) {
            float rmax = s[0][2 * h];
#pragma unroll
            for (int nt = 0; nt < 8; nt++) {
                rmax = fmaxf(rmax, s[nt][2 * h]);
                rmax = fmaxf(rmax, s[nt][2 * h + 1]);
            }
            rmax = fmaxf(rmax, __shfl_xor_sync(0xffffffffu, rmax, 1));
            rmax = fmaxf(rmax, __shfl_xor_sync(0xffffffffu, rmax, 2));
            const float mn = fmaxf(m[h], rmax);
            const float corr = __expf(m[h] - mn);
            m[h] = mn;
            float rs = 0.f;
#pragma unroll
            for (int nt = 0; nt < 8; nt++) {
                s[nt][2 * h]     = __expf(s[nt][2 * h] - mn);
                s[nt][2 * h + 1] = __expf(s[nt][2 * h + 1] - mn);
                rs += s[nt][2 * h] + s[nt][2 * h + 1];
            }
            rs += __shfl_xor_sync(0xffffffffu, rs, 1);
            rs += __shfl_xor_sync(0xffffffffu, rs, 2);
            l[h] = l[h] * corr + rs;
#pragma unroll
            for (int nt = 0; nt < 8; nt++) {
                o[nt][2 * h] *= corr;
                o[nt][2 * h + 1] *= corr;
            }
        }

        // --- store P (tf32) to this warp's private Ps rows ---
#pragma unroll
        for (int nt = 0; nt < 8; nt++)
#pragma unroll
            for (int h = 0; h < 2; h++) {
                uint2 pv = make_uint2(f2tf32(s[nt][2 * h]), f2tf32(s[nt][2 * h + 1]));
                *(uint2*)&Ps[(w * 16 + (lane >> 2) + 8 * h) * 68
                             + nt * 8 + 2 * (lane & 3)] = pv;
            }
        __syncwarp();

        // --- O += P V ---
#pragma unroll
        for (int ksp = 0; ksp < 4; ksp++) {
            uint32_t ap0[4], ap1[4];
            ldsm4(ap0, &Ps[(w * 16 + ((lane >> 3) & 1) * 8 + (lane & 7)) * 68
                           + ksp * 16 + (lane >> 4) * 4]);
            ldsm4(ap1, &Ps[(w * 16 + ((lane >> 3) & 1) * 8 + (lane & 7)) * 68
                           + ksp * 16 + 8 + (lane >> 4) * 4]);
#pragma unroll
            for (int nt = 0; nt < 8; nt++) {
                uint32_t v4[4];
                ldsm4(v4, &Vt[(nt * 8 + (lane & 7)) * 68 + ksp * 16 + (lane >> 3) * 4]);
                mma8(o[nt], ap0, v4[0], v4[1]);
                mma8(o[nt], ap1, v4[2], v4[3]);
            }
        }
    }

    // --- finalize ---
    const int b = hb / 12, head = hb % 12;
#pragma unroll
    for (int h = 0; h < 2; h++) {
        const float inv = 1.0f / l[h];
        const int qg = qbase + rq[h];
        float* orow = &g_attnout[(b * NSEQ + qg) * CDIM + head * 64];
#pragma unroll
        for (int nt = 0; nt < 8; nt++)
            *(float2*)&orow[nt * 8 + 2 * (lane & 3)] =
                make_float2(o[nt][2 * h] * inv, o[nt][2 * h + 1] * inv);
    }
}

// ---------------------------------------------------------------------------
extern "C" void kernel_launch(void* const* d_in, const int* in_sizes, int n_in,
                              void* d_out, int out_size)
{
    const float* x      = (const float*)d_in[0];
    const float* qkv_w  = (const float*)d_in[1];
    const float* qkv_b  = (const float*)d_in[2];
    const float* proj_w = (const float*)d_in[3];
    const float* proj_b = (const float*)d_in[4];
    const float* rpd    = (const float*)d_in[5];
    const float* rph    = (const float*)d_in[6];
    const float* rpw    = (const float*)d_in[7];
    float* out = (float*)d_out;

    cudaFuncSetAttribute(flash_kernel,
                         cudaFuncAttributeMaxDynamicSharedMemorySize, FL_BYTES);

    mm_tf32<0><<<dim3(32, 18), 256>>>(x, qkv_w, qkv_b, nullptr);
    relpos_kernel<<<(NHB * NSEQ * 40 + 255) / 256, 256>>>(rpd, rph, rpw);
    flash_kernel<<<dim3(16, NHB), 256, FL_BYTES>>>();
    mm_tf32<1><<<dim3(32, 6), 256>>>(nullptr, proj_w, proj_b, out);
}

// round 5
// speedup vs baseline: 2.1392x; 1.0018x over previous
#include <cuda_runtime.h>
#include <stdint.h>

// ---------------------------------------------------------------------------
// Attention3D, tf32 tensor cores + cp.async 2-stage pipelines.
// All tensor-op operands are rna-rounded to tf32 BEFORE hitting global memory
// (prep kernel for inputs, epilogues for intermediates), so hot loops stream
// pre-rounded bits via cp.async with no cvt on the critical path.
//   0) prep: round x, qkv_w, proj_w -> scratch
//   1) QKV GEMM -> Q/K natural, V transposed [hb][c][key]  (rounded stores)
//   2) flash attention Br=128 Bc=64, rel-pos tables computed in prologue
//   3) proj GEMM -> d_out (fp32 out)
// ---------------------------------------------------------------------------

#define NHB  24
#define NSEQ 2048
#define HD   64
#define CDIM 768

__device__ float g_q[NHB * NSEQ * HD];
__device__ float g_k[NHB * NSEQ * HD];
__device__ float g_v[NHB * HD * NSEQ];        // [hb][c][key]
__device__ float g_attnout[4096 * CDIM];
__device__ float g_xr[4096 * CDIM];           // rounded x
__device__ float g_qkvw[CDIM * 2304];         // rounded qkv_w
__device__ float g_projw[CDIM * CDIM];        // rounded proj_w

// --- helpers ---------------------------------------------------------------
__device__ __forceinline__ uint32_t f2tf32(float x) {
    uint32_t u;
    asm("cvt.rna.tf32.f32 %0, %1;" : "=r"(u) : "f"(x));
    return u;
}
__device__ __forceinline__ float rtf(float x) {
    return __uint_as_float(f2tf32(x));
}
__device__ __forceinline__ void cpa16(float* dst, const float* src) {
    uint32_t d = (uint32_t)__cvta_generic_to_shared(dst);
    asm volatile("cp.async.cg.shared.global [%0], [%1], 16;" :: "r"(d), "l"(src));
}
__device__ __forceinline__ void cp_commit() {
    asm volatile("cp.async.commit_group;");
}
__device__ __forceinline__ void cp_wait0() {
    asm volatile("cp.async.wait_group 0;");
}
__device__ __forceinline__ void ldsm4(uint32_t r[4], const float* p) {
    uint32_t a = (uint32_t)__cvta_generic_to_shared(p);
    asm volatile("ldmatrix.sync.aligned.m8n8.x4.shared.b16 {%0,%1,%2,%3}, [%4];"
                 : "=r"(r[0]), "=r"(r[1]), "=r"(r[2]), "=r"(r[3]) : "r"(a));
}
__device__ __forceinline__ void mma8(float d[4], const uint32_t a[4],
                                     uint32_t b0, uint32_t b1) {
    asm volatile(
        "mma.sync.aligned.m16n8k8.row.col.f32.tf32.tf32.f32 "
        "{%0,%1,%2,%3}, {%4,%5,%6,%7}, {%8,%9}, {%0,%1,%2,%3};"
        : "+f"(d[0]), "+f"(d[1]), "+f"(d[2]), "+f"(d[3])
        : "r"(a[0]), "r"(a[1]), "r"(a[2]), "r"(a[3]), "r"(b0), "r"(b1));
}

// ---------------------------------------------------------------------------
// Prep: rna-round inputs into scratch (float4 grid-stride).
// ---------------------------------------------------------------------------
__global__ void __launch_bounds__(256) prep_round(
    const float* __restrict__ x, const float* __restrict__ qw,
    const float* __restrict__ pw)
{
    const int stride = gridDim.x * 256;
    const int t = blockIdx.x * 256 + threadIdx.x;
    for (int f = t; f < (4096 * CDIM) / 4; f += stride) {
        float4 v = *(const float4*)&x[f * 4];
        *(float4*)&g_xr[f * 4] = make_float4(rtf(v.x), rtf(v.y), rtf(v.z), rtf(v.w));
    }
    for (int f = t; f < (CDIM * 2304) / 4; f += stride) {
        float4 v = *(const float4*)&qw[f * 4];
        *(float4*)&g_qkvw[f * 4] = make_float4(rtf(v.x), rtf(v.y), rtf(v.z), rtf(v.w));
    }
    for (int f = t; f < (CDIM * CDIM) / 4; f += stride) {
        float4 v = *(const float4*)&pw[f * 4];
        *(float4*)&g_projw[f * 4] = make_float4(rtf(v.x), rtf(v.y), rtf(v.z), rtf(v.w));
    }
}

// ---------------------------------------------------------------------------
// tf32 GEMM, 128x128 k16, 2-stage cp.async (pre-rounded sources).
// MODE 0: A=g_xr, W=g_qkvw, N=2304, scatter q/k/v (rounded stores).
// MODE 1: A=g_attnout (pre-rounded), W=g_projw, N=768 -> out (fp32).
// ---------------------------------------------------------------------------
template <int MODE>
__global__ void __launch_bounds__(256) mm_tf32(
    const float* __restrict__ bias, float* __restrict__ out)
{
    constexpr int N = (MODE == 0) ? 2304 : 768;
    __shared__ float As[2][128 * 20];
    __shared__ float Bs[2][16 * 136];
    const int tid = threadIdx.x, lane = tid & 31, w = tid >> 5;
    const int wm = w >> 1, wn = w & 1;
    const int bm = blockIdx.x * 128, bn = blockIdx.y * 128;
    const float* Ap = (MODE == 0) ? g_xr : g_attnout;
    const float* W_ = (MODE == 0) ? g_qkvw : g_projw;

    float c[2][8][4];
#pragma unroll
    for (int i = 0; i < 2; i++)
#pragma unroll
        for (int j = 0; j < 8; j++)
#pragma unroll
            for (int k = 0; k < 4; k++) c[i][j][k] = 0.f;

    auto stage = [&](int k0, int buf) {
#pragma unroll
        for (int it = 0; it < 2; it++) {
            const int i = tid + it * 256;
            const int r = i >> 2, c4 = (i & 3) << 2;
            cpa16(&As[buf][r * 20 + c4], &Ap[(bm + r) * 768 + k0 + c4]);
        }
#pragma unroll
        for (int it = 0; it < 2; it++) {
            const int i = tid + it * 256;
            const int kk = i >> 5, n4 = (i & 31) << 2;
            cpa16(&Bs[buf][kk * 136 + n4], &W_[(k0 + kk) * N + bn + n4]);
        }
    };

    stage(0, 0); cp_commit();

    int buf = 0;
    for (int k0 = 0; k0 < 768; k0 += 16, buf ^= 1) {
        cp_wait0();
        __syncthreads();
        if (k0 + 16 < 768) { stage(k0 + 16, buf ^ 1); cp_commit(); }

        const uint32_t* bp = (const uint32_t*)Bs[buf];
#pragma unroll
        for (int ks = 0; ks < 2; ks++) {
            uint32_t a0[4], a1[4];
            ldsm4(a0, &As[buf][(wm * 32 + ((lane >> 3) & 1) * 8 + (lane & 7)) * 20
                               + ks * 8 + (lane >> 4) * 4]);
            ldsm4(a1, &As[buf][(wm * 32 + 16 + ((lane >> 3) & 1) * 8 + (lane & 7)) * 20
                               + ks * 8 + (lane >> 4) * 4]);
#pragma unroll
            for (int nt = 0; nt < 8; nt++) {
                const int ncol = wn * 64 + nt * 8 + (lane >> 2);
                uint32_t b0 = bp[(ks * 8 + (lane & 3)) * 136 + ncol];
                uint32_t b1 = bp[(ks * 8 + 4 + (lane & 3)) * 136 + ncol];
                mma8(c[0][nt], a0, b0, b1);
                mma8(c[1][nt], a1, b0, b1);
            }
        }
        __syncthreads();
    }

    if (MODE == 0) {
        const int hc = bn + wn * 64;
        const int which = hc / 768;
        const int head = (hc % 768) >> 6;
#pragma unroll
        for (int mt = 0; mt < 2; mt++)
#pragma unroll
            for (int nt = 0; nt < 8; nt++) {
                const int ccol = nt * 8 + ((lane & 3) << 1);
                const float b0v = bias[hc + ccol];
                const float b1v = bias[hc + ccol + 1];
#pragma unroll
                for (int h = 0; h < 2; h++) {
                    const int row = bm + wm * 32 + mt * 16 + (lane >> 2) + 8 * h;
                    const int b_ = row >> 11, n = row & 2047;
                    const int hb = b_ * 12 + head;
                    const float v0 = rtf(c[mt][nt][2 * h] + b0v);
                    const float v1 = rtf(c[mt][nt][2 * h + 1] + b1v);
                    if (which == 0)
                        *(float2*)&g_q[((hb * NSEQ + n) << 6) + ccol] = make_float2(v0, v1);
                    else if (which == 1)
                        *(float2*)&g_k[((hb * NSEQ + n) << 6) + ccol] = make_float2(v0, v1);
                    else {
                        g_v[hb * (HD * NSEQ) + ccol * NSEQ + n] = v0;
                        g_v[hb * (HD * NSEQ) + (ccol + 1) * NSEQ + n] = v1;
                    }
                }
            }
    } else {
#pragma unroll
        for (int mt = 0; mt < 2; mt++)
#pragma unroll
            for (int nt = 0; nt < 8; nt++) {
                const int col = bn + wn * 64 + nt * 8 + ((lane & 3) << 1);
                const float b0v = bias[col], b1v = bias[col + 1];
#pragma unroll
                for (int h = 0; h < 2; h++) {
                    const int row = bm + wm * 32 + mt * 16 + (lane >> 2) + 8 * h;
                    *(float2*)&out[row * 768 + col] =
                        make_float2(c[mt][nt][2 * h] + b0v, c[mt][nt][2 * h + 1] + b1v);
                }
            }
    }
}

// ---------------------------------------------------------------------------
// Flash attention: Br=128, Bc=64, 8 warps, tf32 mma, 2-stage cp.async K/V,
// rel-pos tables computed in prologue from (rounded) Q + exact tables.
// smem floats: Qs 128x68 | Ks 2x64x68 | Vt 2x64x68 | Ps 128x68 |
//              rDt 8x128 | rHt 16x128 | rWt 16x128
// ---------------------------------------------------------------------------
#define QS_OFF 0
#define KS_OFF 8704
#define VT_OFF 17408
#define PS_OFF 26112
#define RD_OFF 34816
#define RH_OFF 35840
#define RW_OFF 37888
#define FL_FLOATS 39936
#define FL_BYTES  (FL_FLOATS * 4)

__global__ void __launch_bounds__(256, 1) flash_kernel(
    const float* __restrict__ rpd, const float* __restrict__ rph,
    const float* __restrict__ rpw)
{
    extern __shared__ float sm[];
    float* Qs  = sm + QS_OFF;
    float* Ks  = sm + KS_OFF;
    float* Vt  = sm + VT_OFF;
    float* Ps  = sm + PS_OFF;
    float* rDt = sm + RD_OFF;
    float* rHt = sm + RH_OFF;
    float* rWt = sm + RW_OFF;

    const int tid = threadIdx.x, lane = tid & 31, w = tid >> 5;
    const int hb = blockIdx.y;
    const int qbase = blockIdx.x * 128;
    const float scale = 0.125f;

    // --- stage Q (pre-rounded tf32 bits) ---
    const float* Qg = &g_q[(hb * NSEQ + qbase) * HD];
#pragma unroll
    for (int it = 0; it < 8; it++) {
        const int f = it * 1024 + tid * 4;
        const int r = f >> 6, c0 = f & 63;
        *(float4*)&Qs[r * 68 + c0] = *(const float4*)&Qg[f];
    }
    __syncthreads();

    // --- rel-pos tables for this block's 128 queries (fp32 dots) ---
    for (int i = tid; i < 128 * 40; i += 256) {
        const int row = i / 40, j = i - row * 40;
        const int n = qbase + row;
        const int d = n >> 8, h = (n >> 4) & 15, wq = n & 15;
        const float* trow;
        float* dst;
        if (j < 8)       { trow = &rpd[(d - j + 7) * HD];        dst = &rDt[j * 128 + row]; }
        else if (j < 24) { const int kh = j - 8;  trow = &rph[(h - kh + 15) * HD];  dst = &rHt[kh * 128 + row]; }
        else             { const int kw = j - 24; trow = &rpw[(wq - kw + 15) * HD]; dst = &rWt[kw * 128 + row]; }
        const float* qrow = &Qs[row * 68];
        float s = 0.f;
#pragma unroll
        for (int c = 0; c < HD; c++) s += qrow[c] * trow[c];
        *dst = s;
    }

    // --- K/V staging (cp.async, double buffered) ---
    auto stageKV = [&](int kt, int buf) {
        const float* Kg = &g_k[(hb * NSEQ + kt * 64) * HD];
        const float* Vg = &g_v[hb * (HD * NSEQ) + kt * 64];
        float* Kb = Ks + buf * 4352;
        float* Vb = Vt + buf * 4352;
#pragma unroll
        for (int it = 0; it < 4; it++) {
            const int f = it * 1024 + tid * 4;
            const int r = f >> 6, c0 = f & 63;
            cpa16(&Kb[r * 68 + c0], &Kg[f]);
            cpa16(&Vb[r * 68 + c0], &Vg[r * NSEQ + c0]);
        }
    };
    stageKV(0, 0); cp_commit();
    __syncthreads();   // rel tables visible

    // --- hoist Q A-fragments + per-thread rW values ---
    uint32_t aq[8][4];
#pragma unroll
    for (int ks = 0; ks < 8; ks++)
        ldsm4(aq[ks], &Qs[(w * 16 + ((lane >> 3) & 1) * 8 + (lane & 7)) * 68
                          + ks * 8 + (lane >> 4) * 4]);
    int rq[2];
    rq[0] = w * 16 + (lane >> 2);
    rq[1] = rq[0] + 8;
    float rw[2][2][2];
#pragma unroll
    for (int p = 0; p < 2; p++)
#pragma unroll
        for (int j2 = 0; j2 < 2; j2++)
#pragma unroll
            for (int h = 0; h < 2; h++)
                rw[p][j2][h] = rWt[(8 * p + 2 * (lane & 3) + j2) * 128 + rq[h]];

    float m[2] = {-1e30f, -1e30f}, l[2] = {0.f, 0.f};
    float o[8][4];
#pragma unroll
    for (int i = 0; i < 8; i++)
#pragma unroll
        for (int j = 0; j < 4; j++) o[i][j] = 0.f;

    int buf = 0;
    for (int kt = 0; kt < 32; kt++, buf ^= 1) {
        cp_wait0();
        __syncthreads();
        if (kt + 1 < 32) { stageKV(kt + 1, buf ^ 1); cp_commit(); }
        const float* Kb = Ks + buf * 4352;
        const float* Vb = Vt + buf * 4352;

        // --- S = Q K^T ---
        float s[8][4];
#pragma unroll
        for (int i = 0; i < 8; i++)
#pragma unroll
            for (int j = 0; j < 4; j++) s[i][j] = 0.f;
#pragma unroll
        for (int ksp = 0; ksp < 4; ksp++) {
#pragma unroll
            for (int nt = 0; nt < 8; nt++) {
                uint32_t k4[4];
                ldsm4(k4, &Kb[(nt * 8 + (lane & 7)) * 68 + ksp * 16 + (lane >> 3) * 4]);
                mma8(s[nt], aq[2 * ksp], k4[0], k4[1]);
                mma8(s[nt], aq[2 * ksp + 1], k4[2], k4[3]);
            }
        }

        // --- scale + bias ---
        const int kd = kt >> 2;
        float bh[4][2];
#pragma unroll
        for (int g = 0; g < 4; g++)
#pragma unroll
            for (int h = 0; h < 2; h++)
                bh[g][h] = rDt[kd * 128 + rq[h]]
                         + rHt[((kt & 3) * 4 + g) * 128 + rq[h]];
#pragma unroll
        for (int nt = 0; nt < 8; nt++)
#pragma unroll
            for (int h = 0; h < 2; h++)
#pragma unroll
                for (int j2 = 0; j2 < 2; j2++)
                    s[nt][2 * h + j2] = fmaf(s[nt][2 * h + j2], scale,
                                             bh[nt >> 1][h] + rw[nt & 1][j2][h]);

        // --- online softmax ---
#pragma unroll
        for (int h = 0; h < 2; h++) {
            float rmax = s[0][2 * h];
#pragma unroll
            for (int nt = 0; nt < 8; nt++) {
                rmax = fmaxf(rmax, s[nt][2 * h]);
                rmax = fmaxf(rmax, s[nt][2 * h + 1]);
            }
            rmax = fmaxf(rmax, __shfl_xor_sync(0xffffffffu, rmax, 1));
            rmax = fmaxf(rmax, __shfl_xor_sync(0xffffffffu, rmax, 2));
            const float mn = fmaxf(m[h], rmax);
            const float corr = __expf(m[h] - mn);
            m[h] = mn;
            float rs = 0.f;
#pragma unroll
            for (int nt = 0; nt < 8; nt++) {
                s[nt][2 * h]     = __expf(s[nt][2 * h] - mn);
                s[nt][2 * h + 1] = __expf(s[nt][2 * h + 1] - mn);
                rs += s[nt][2 * h] + s[nt][2 * h + 1];
            }
            rs += __shfl_xor_sync(0xffffffffu, rs, 1);
            rs += __shfl_xor_sync(0xffffffffu, rs, 2);
            l[h] = l[h] * corr + rs;
#pragma unroll
            for (int nt = 0; nt < 8; nt++) {
                o[nt][2 * h] *= corr;
                o[nt][2 * h + 1] *= corr;
            }
        }

        // --- store P (rna tf32) to warp-private Ps rows ---
#pragma unroll
        for (int nt = 0; nt < 8; nt++)
#pragma unroll
            for (int h = 0; h < 2; h++) {
                uint2 pv = make_uint2(f2tf32(s[nt][2 * h]), f2tf32(s[nt][2 * h + 1]));
                *(uint2*)&Ps[(w * 16 + (lane >> 2) + 8 * h) * 68
                             + nt * 8 + 2 * (lane & 3)] = pv;
            }
        __syncwarp();

        // --- O += P V ---
#pragma unroll
        for (int ksp = 0; ksp < 4; ksp++) {
            uint32_t ap0[4], ap1[4];
            ldsm4(ap0, &Ps[(w * 16 + ((lane >> 3) & 1) * 8 + (lane & 7)) * 68
                           + ksp * 16 + (lane >> 4) * 4]);
            ldsm4(ap1, &Ps[(w * 16 + ((lane >> 3) & 1) * 8 + (lane & 7)) * 68
                           + ksp * 16 + 8 + (lane >> 4) * 4]);
#pragma unroll
            for (int nt = 0; nt < 8; nt++) {
                uint32_t v4[4];
                ldsm4(v4, &Vb[(nt * 8 + (lane & 7)) * 68 + ksp * 16 + (lane >> 3) * 4]);
                mma8(o[nt], ap0, v4[0], v4[1]);
                mma8(o[nt], ap1, v4[2], v4[3]);
            }
        }
    }

    // --- finalize (store rna-rounded: feeds proj as tf32 A-operand) ---
    const int b = hb / 12, head = hb % 12;
#pragma unroll
    for (int h = 0; h < 2; h++) {
        const float inv = 1.0f / l[h];
        const int qg = qbase + rq[h];
        float* orow = &g_attnout[(b * NSEQ + qg) * CDIM + head * 64];
#pragma unroll
        for (int nt = 0; nt < 8; nt++)
            *(float2*)&orow[nt * 8 + 2 * (lane & 3)] =
                make_float2(rtf(o[nt][2 * h] * inv), rtf(o[nt][2 * h + 1] * inv));
    }
}

// ---------------------------------------------------------------------------
extern "C" void kernel_launch(void* const* d_in, const int* in_sizes, int n_in,
                              void* d_out, int out_size)
{
    const float* x      = (const float*)d_in[0];
    const float* qkv_w  = (const float*)d_in[1];
    const float* qkv_b  = (const float*)d_in[2];
    const float* proj_w = (const float*)d_in[3];
    const float* proj_b = (const float*)d_in[4];
    const float* rpd    = (const float*)d_in[5];
    const float* rph    = (const float*)d_in[6];
    const float* rpw    = (const float*)d_in[7];
    float* out = (float*)d_out;

    cudaFuncSetAttribute(flash_kernel,
                         cudaFuncAttributeMaxDynamicSharedMemorySize, FL_BYTES);

    prep_round<<<1184, 256>>>(x, qkv_w, proj_w);
    mm_tf32<0><<<dim3(32, 18), 256>>>(qkv_b, nullptr);
    flash_kernel<<<dim3(16, NHB), 256, FL_BYTES>>>(rpd, rph, rpw);
    mm_tf32<1><<<dim3(32, 6), 256>>>(proj_b, out);
}

// round 6
// speedup vs baseline: 2.1860x; 1.0219x over previous
#include <cuda_runtime.h>
#include <stdint.h>

// ---------------------------------------------------------------------------
// Attention3D, tf32 tensor cores + cp.async pipelines.
// All tensor operands rna-rounded to tf32 before global memory (prep kernel
// for inputs, epilogues for intermediates) -> hot loops stream raw bits.
//   0) prep: round x, qkv_w, proj_w
//   1) QKV GEMM -> Q/K natural, V transposed [hb][c][key]
//   2) flash attention Br=128 Bc=64, 105KB smem (2 CTAs/SM):
//        Ps overlays Qs, V single-buffered w/ own commit group
//   3) proj GEMM -> d_out
// ---------------------------------------------------------------------------

#define NHB  24
#define NSEQ 2048
#define HD   64
#define CDIM 768

__device__ float g_q[NHB * NSEQ * HD];
__device__ float g_k[NHB * NSEQ * HD];
__device__ float g_v[NHB * HD * NSEQ];        // [hb][c][key]
__device__ float g_attnout[4096 * CDIM];
__device__ float g_xr[4096 * CDIM];
__device__ float g_qkvw[CDIM * 2304];
__device__ float g_projw[CDIM * CDIM];

// --- helpers ---------------------------------------------------------------
__device__ __forceinline__ uint32_t f2tf32(float x) {
    uint32_t u;
    asm("cvt.rna.tf32.f32 %0, %1;" : "=r"(u) : "f"(x));
    return u;
}
__device__ __forceinline__ float rtf(float x) {
    return __uint_as_float(f2tf32(x));
}
__device__ __forceinline__ void cpa16(float* dst, const float* src) {
    uint32_t d = (uint32_t)__cvta_generic_to_shared(dst);
    asm volatile("cp.async.cg.shared.global [%0], [%1], 16;" :: "r"(d), "l"(src));
}
__device__ __forceinline__ void cp_commit() {
    asm volatile("cp.async.commit_group;");
}
__device__ __forceinline__ void cp_wait0() {
    asm volatile("cp.async.wait_group 0;");
}
__device__ __forceinline__ void cp_wait1() {
    asm volatile("cp.async.wait_group 1;");
}
__device__ __forceinline__ void ldsm4(uint32_t r[4], const float* p) {
    uint32_t a = (uint32_t)__cvta_generic_to_shared(p);
    asm volatile("ldmatrix.sync.aligned.m8n8.x4.shared.b16 {%0,%1,%2,%3}, [%4];"
                 : "=r"(r[0]), "=r"(r[1]), "=r"(r[2]), "=r"(r[3]) : "r"(a));
}
__device__ __forceinline__ void mma8(float d[4], const uint32_t a[4],
                                     uint32_t b0, uint32_t b1) {
    asm volatile(
        "mma.sync.aligned.m16n8k8.row.col.f32.tf32.tf32.f32 "
        "{%0,%1,%2,%3}, {%4,%5,%6,%7}, {%8,%9}, {%0,%1,%2,%3};"
        : "+f"(d[0]), "+f"(d[1]), "+f"(d[2]), "+f"(d[3])
        : "r"(a[0]), "r"(a[1]), "r"(a[2]), "r"(a[3]), "r"(b0), "r"(b1));
}

// ---------------------------------------------------------------------------
// Prep: rna-round inputs into scratch.
// ---------------------------------------------------------------------------
__global__ void __launch_bounds__(256) prep_round(
    const float* __restrict__ x, const float* __restrict__ qw,
    const float* __restrict__ pw)
{
    const int stride = gridDim.x * 256;
    const int t = blockIdx.x * 256 + threadIdx.x;
    for (int f = t; f < (4096 * CDIM) / 4; f += stride) {
        float4 v = *(const float4*)&x[f * 4];
        *(float4*)&g_xr[f * 4] = make_float4(rtf(v.x), rtf(v.y), rtf(v.z), rtf(v.w));
    }
    for (int f = t; f < (CDIM * 2304) / 4; f += stride) {
        float4 v = *(const float4*)&qw[f * 4];
        *(float4*)&g_qkvw[f * 4] = make_float4(rtf(v.x), rtf(v.y), rtf(v.z), rtf(v.w));
    }
    for (int f = t; f < (CDIM * CDIM) / 4; f += stride) {
        float4 v = *(const float4*)&pw[f * 4];
        *(float4*)&g_projw[f * 4] = make_float4(rtf(v.x), rtf(v.y), rtf(v.z), rtf(v.w));
    }
}

// ---------------------------------------------------------------------------
// tf32 GEMM, 128x128 k16, 2-stage cp.async (pre-rounded sources).
// ---------------------------------------------------------------------------
template <int MODE>
__global__ void __launch_bounds__(256) mm_tf32(
    const float* __restrict__ bias, float* __restrict__ out)
{
    constexpr int N = (MODE == 0) ? 2304 : 768;
    __shared__ float As[2][128 * 20];
    __shared__ float Bs[2][16 * 136];
    const int tid = threadIdx.x, lane = tid & 31, w = tid >> 5;
    const int wm = w >> 1, wn = w & 1;
    const int bm = blockIdx.x * 128, bn = blockIdx.y * 128;
    const float* Ap = (MODE == 0) ? g_xr : g_attnout;
    const float* W_ = (MODE == 0) ? g_qkvw : g_projw;

    float c[2][8][4];
#pragma unroll
    for (int i = 0; i < 2; i++)
#pragma unroll
        for (int j = 0; j < 8; j++)
#pragma unroll
            for (int k = 0; k < 4; k++) c[i][j][k] = 0.f;

    auto stage = [&](int k0, int buf) {
#pragma unroll
        for (int it = 0; it < 2; it++) {
            const int i = tid + it * 256;
            const int r = i >> 2, c4 = (i & 3) << 2;
            cpa16(&As[buf][r * 20 + c4], &Ap[(bm + r) * 768 + k0 + c4]);
        }
#pragma unroll
        for (int it = 0; it < 2; it++) {
            const int i = tid + it * 256;
            const int kk = i >> 5, n4 = (i & 31) << 2;
            cpa16(&Bs[buf][kk * 136 + n4], &W_[(k0 + kk) * N + bn + n4]);
        }
    };

    stage(0, 0); cp_commit();

    int buf = 0;
    for (int k0 = 0; k0 < 768; k0 += 16, buf ^= 1) {
        cp_wait0();
        __syncthreads();
        if (k0 + 16 < 768) { stage(k0 + 16, buf ^ 1); cp_commit(); }

        const uint32_t* bp = (const uint32_t*)Bs[buf];
#pragma unroll
        for (int ks = 0; ks < 2; ks++) {
            uint32_t a0[4], a1[4];
            ldsm4(a0, &As[buf][(wm * 32 + ((lane >> 3) & 1) * 8 + (lane & 7)) * 20
                               + ks * 8 + (lane >> 4) * 4]);
            ldsm4(a1, &As[buf][(wm * 32 + 16 + ((lane >> 3) & 1) * 8 + (lane & 7)) * 20
                               + ks * 8 + (lane >> 4) * 4]);
#pragma unroll
            for (int nt = 0; nt < 8; nt++) {
                const int ncol = wn * 64 + nt * 8 + (lane >> 2);
                uint32_t b0 = bp[(ks * 8 + (lane & 3)) * 136 + ncol];
                uint32_t b1 = bp[(ks * 8 + 4 + (lane & 3)) * 136 + ncol];
                mma8(c[0][nt], a0, b0, b1);
                mma8(c[1][nt], a1, b0, b1);
            }
        }
        __syncthreads();
    }

    if (MODE == 0) {
        const int hc = bn + wn * 64;
        const int which = hc / 768;
        const int head = (hc % 768) >> 6;
#pragma unroll
        for (int mt = 0; mt < 2; mt++)
#pragma unroll
            for (int nt = 0; nt < 8; nt++) {
                const int ccol = nt * 8 + ((lane & 3) << 1);
                const float b0v = bias[hc + ccol];
                const float b1v = bias[hc + ccol + 1];
#pragma unroll
                for (int h = 0; h < 2; h++) {
                    const int row = bm + wm * 32 + mt * 16 + (lane >> 2) + 8 * h;
                    const int b_ = row >> 11, n = row & 2047;
                    const int hb = b_ * 12 + head;
                    const float v0 = rtf(c[mt][nt][2 * h] + b0v);
                    const float v1 = rtf(c[mt][nt][2 * h + 1] + b1v);
                    if (which == 0)
                        *(float2*)&g_q[((hb * NSEQ + n) << 6) + ccol] = make_float2(v0, v1);
                    else if (which == 1)
                        *(float2*)&g_k[((hb * NSEQ + n) << 6) + ccol] = make_float2(v0, v1);
                    else {
                        g_v[hb * (HD * NSEQ) + ccol * NSEQ + n] = v0;
                        g_v[hb * (HD * NSEQ) + (ccol + 1) * NSEQ + n] = v1;
                    }
                }
            }
    } else {
#pragma unroll
        for (int mt = 0; mt < 2; mt++)
#pragma unroll
            for (int nt = 0; nt < 8; nt++) {
                const int col = bn + wn * 64 + nt * 8 + ((lane & 3) << 1);
                const float b0v = bias[col], b1v = bias[col + 1];
#pragma unroll
                for (int h = 0; h < 2; h++) {
                    const int row = bm + wm * 32 + mt * 16 + (lane >> 2) + 8 * h;
                    *(float2*)&out[row * 768 + col] =
                        make_float2(c[mt][nt][2 * h] + b0v, c[mt][nt][2 * h + 1] + b1v);
                }
            }
    }
}

// ---------------------------------------------------------------------------
// Flash attention, 105KB smem -> 2 CTAs/SM.
// smem floats: Ps(=Qs overlay) 128x68 | Ks 2x64x68 | Vt 64x68 |
//              rDt 8x128 | rHt 16x128 | rWt 16x128   = 26880 fl = 107520 B
// K double-buffered, V single-buffered (own commit group, loaded under S).
// ---------------------------------------------------------------------------
#define QS_OFF 0
#define KS_OFF 8704
#define VT_OFF 17408
#define RD_OFF 21760
#define RH_OFF 22784
#define RW_OFF 24832
#define FL_FLOATS 26880
#define FL_BYTES  (FL_FLOATS * 4)

__global__ void __launch_bounds__(256, 2) flash_kernel(
    const float* __restrict__ rpd, const float* __restrict__ rph,
    const float* __restrict__ rpw)
{
    extern __shared__ float sm[];
    float* Qs  = sm + QS_OFF;     // prologue only
    float* Ps  = sm + QS_OFF;     // main loop (overlay)
    float* Ks  = sm + KS_OFF;
    float* Vt  = sm + VT_OFF;
    float* rDt = sm + RD_OFF;
    float* rHt = sm + RH_OFF;
    float* rWt = sm + RW_OFF;

    const int tid = threadIdx.x, lane = tid & 31, w = tid >> 5;
    const int hb = blockIdx.y;
    const int qbase = blockIdx.x * 128;
    const float scale = 0.125f;

    auto stageK = [&](int kt, int buf) {
        const float* Kg = &g_k[(hb * NSEQ + kt * 64) * HD];
        float* Kb = Ks + buf * 4352;
#pragma unroll
        for (int it = 0; it < 4; it++) {
            const int f = it * 1024 + tid * 4;
            const int r = f >> 6, c0 = f & 63;
            cpa16(&Kb[r * 68 + c0], &Kg[f]);
        }
    };
    auto stageV = [&](int kt) {
        const float* Vg = &g_v[hb * (HD * NSEQ) + kt * 64];
#pragma unroll
        for (int it = 0; it < 4; it++) {
            const int f = it * 1024 + tid * 4;
            const int r = f >> 6, c0 = f & 63;
            cpa16(&Vt[r * 68 + c0], &Vg[r * NSEQ + c0]);
        }
    };

    // kick off K0, V0 immediately
    stageK(0, 0); cp_commit();
    stageV(0);    cp_commit();

    // --- stage Q (pre-rounded bits) ---
    const float* Qg = &g_q[(hb * NSEQ + qbase) * HD];
#pragma unroll
    for (int it = 0; it < 8; it++) {
        const int f = it * 1024 + tid * 4;
        const int r = f >> 6, c0 = f & 63;
        *(float4*)&Qs[r * 68 + c0] = *(const float4*)&Qg[f];
    }
    __syncthreads();

    // --- rel-pos tables for 128 queries ---
    for (int i = tid; i < 128 * 40; i += 256) {
        const int row = i / 40, j = i - row * 40;
        const int n = qbase + row;
        const int d = n >> 8, h = (n >> 4) & 15, wq = n & 15;
        const float* trow;
        float* dst;
        if (j < 8)       { trow = &rpd[(d - j + 7) * HD];        dst = &rDt[j * 128 + row]; }
        else if (j < 24) { const int kh = j - 8;  trow = &rph[(h - kh + 15) * HD];  dst = &rHt[kh * 128 + row]; }
        else             { const int kw = j - 24; trow = &rpw[(wq - kw + 15) * HD]; dst = &rWt[kw * 128 + row]; }
        const float* qrow = &Qs[row * 68];
        float s = 0.f;
#pragma unroll
        for (int c = 0; c < HD; c++) s += qrow[c] * trow[c];
        *dst = s;
    }
    __syncthreads();   // tables visible; all still before first Ps write

    // --- hoist Q A-fragments (Qs still intact) + per-thread rW values ---
    uint32_t aq[8][4];
#pragma unroll
    for (int ks = 0; ks < 8; ks++)
        ldsm4(aq[ks], &Qs[(w * 16 + ((lane >> 3) & 1) * 8 + (lane & 7)) * 68
                          + ks * 8 + (lane >> 4) * 4]);
    int rq[2];
    rq[0] = w * 16 + (lane >> 2);
    rq[1] = rq[0] + 8;
    float rw[2][2][2];
#pragma unroll
    for (int p = 0; p < 2; p++)
#pragma unroll
        for (int j2 = 0; j2 < 2; j2++)
#pragma unroll
            for (int h = 0; h < 2; h++)
                rw[p][j2][h] = rWt[(8 * p + 2 * (lane & 3) + j2) * 128 + rq[h]];

    float m[2] = {-1e30f, -1e30f}, l[2] = {0.f, 0.f};
    float o[8][4];
#pragma unroll
    for (int i = 0; i < 8; i++)
#pragma unroll
        for (int j = 0; j < 4; j++) o[i][j] = 0.f;

    int buf = 0;
    for (int kt = 0; kt < 32; kt++, buf ^= 1) {
        // pending FIFO here: [K(kt), V(kt)] -> wait1 completes K(kt)
        cp_wait1();
        __syncthreads();          // K visible to all; Ps/Qs reads all done (iter0)
        if (kt + 1 < 32) { stageK(kt + 1, buf ^ 1); cp_commit(); }
        const float* Kb = Ks + buf * 4352;

        // --- S = Q K^T ---
        float s[8][4];
#pragma unroll
        for (int i = 0; i < 8; i++)
#pragma unroll
            for (int j = 0; j < 4; j++) s[i][j] = 0.f;
#pragma unroll
        for (int ksp = 0; ksp < 4; ksp++) {
#pragma unroll
            for (int nt = 0; nt < 8; nt++) {
                uint32_t k4[4];
                ldsm4(k4, &Kb[(nt * 8 + (lane & 7)) * 68 + ksp * 16 + (lane >> 3) * 4]);
                mma8(s[nt], aq[2 * ksp], k4[0], k4[1]);
                mma8(s[nt], aq[2 * ksp + 1], k4[2], k4[3]);
            }
        }

        // --- scale + bias ---
        const int kd = kt >> 2;
        float bh[4][2];
#pragma unroll
        for (int g = 0; g < 4; g++)
#pragma unroll
            for (int h = 0; h < 2; h++)
                bh[g][h] = rDt[kd * 128 + rq[h]]
                         + rHt[((kt & 3) * 4 + g) * 128 + rq[h]];
#pragma unroll
        for (int nt = 0; nt < 8; nt++)
#pragma unroll
            for (int h = 0; h < 2; h++)
#pragma unroll
                for (int j2 = 0; j2 < 2; j2++)
                    s[nt][2 * h + j2] = fmaf(s[nt][2 * h + j2], scale,
                                             bh[nt >> 1][h] + rw[nt & 1][j2][h]);

        // --- online softmax ---
#pragma unroll
        for (int h = 0; h < 2; h++) {
            float rmax = s[0][2 * h];
#pragma unroll
            for (int nt = 0; nt < 8; nt++) {
                rmax = fmaxf(rmax, s[nt][2 * h]);
                rmax = fmaxf(rmax, s[nt][2 * h + 1]);
            }
            rmax = fmaxf(rmax, __shfl_xor_sync(0xffffffffu, rmax, 1));
            rmax = fmaxf(rmax, __shfl_xor_sync(0xffffffffu, rmax, 2));
            const float mn = fmaxf(m[h], rmax);
            const float corr = __expf(m[h] - mn);
            m[h] = mn;
            float rs = 0.f;
#pragma unroll
            for (int nt = 0; nt < 8; nt++) {
                s[nt][2 * h]     = __expf(s[nt][2 * h] - mn);
                s[nt][2 * h + 1] = __expf(s[nt][2 * h + 1] - mn);
                rs += s[nt][2 * h] + s[nt][2 * h + 1];
            }
            rs += __shfl_xor_sync(0xffffffffu, rs, 1);
            rs += __shfl_xor_sync(0xffffffffu, rs, 2);
            l[h] = l[h] * corr + rs;
#pragma unroll
            for (int nt = 0; nt < 8; nt++) {
                o[nt][2 * h] *= corr;
                o[nt][2 * h + 1] *= corr;
            }
        }

        // --- store P (rna tf32) to warp-private Ps rows ---
#pragma unroll
        for (int nt = 0; nt < 8; nt++)
#pragma unroll
            for (int h = 0; h < 2; h++) {
                uint2 pv = make_uint2(f2tf32(s[nt][2 * h]), f2tf32(s[nt][2 * h + 1]));
                *(uint2*)&Ps[(w * 16 + (lane >> 2) + 8 * h) * 68
                             + nt * 8 + 2 * (lane & 3)] = pv;
            }

        // pending: [V(kt), K(kt+1)] -> wait1 completes V(kt); last iter: wait0
        if (kt + 1 < 32) cp_wait1(); else cp_wait0();
        __syncthreads();          // V + P visible to all

        // --- O += P V ---
#pragma unroll
        for (int ksp = 0; ksp < 4; ksp++) {
            uint32_t ap0[4], ap1[4];
            ldsm4(ap0, &Ps[(w * 16 + ((lane >> 3) & 1) * 8 + (lane & 7)) * 68
                           + ksp * 16 + (lane >> 4) * 4]);
            ldsm4(ap1, &Ps[(w * 16 + ((lane >> 3) & 1) * 8 + (lane & 7)) * 68
                           + ksp * 16 + 8 + (lane >> 4) * 4]);
#pragma unroll
            for (int nt = 0; nt < 8; nt++) {
                uint32_t v4[4];
                ldsm4(v4, &Vt[(nt * 8 + (lane & 7)) * 68 + ksp * 16 + (lane >> 3) * 4]);
                mma8(o[nt], ap0, v4[0], v4[1]);
                mma8(o[nt], ap1, v4[2], v4[3]);
            }
        }

        __syncthreads();          // all warps done reading Vt (and Ps)
        if (kt + 1 < 32) { stageV(kt + 1); cp_commit(); }
    }

    // --- finalize (rna-rounded: feeds proj as tf32 A operand) ---
    const int b = hb / 12, head = hb % 12;
#pragma unroll
    for (int h = 0; h < 2; h++) {
        const float inv = 1.0f / l[h];
        const int qg = qbase + rq[h];
        float* orow = &g_attnout[(b * NSEQ + qg) * CDIM + head * 64];
#pragma unroll
        for (int nt = 0; nt < 8; nt++)
            *(float2*)&orow[nt * 8 + 2 * (lane & 3)] =
                make_float2(rtf(o[nt][2 * h] * inv), rtf(o[nt][2 * h + 1] * inv));
    }
}

// ---------------------------------------------------------------------------
extern "C" void kernel_launch(void* const* d_in, const int* in_sizes, int n_in,
                              void* d_out, int out_size)
{
    const float* x      = (const float*)d_in[0];
    const float* qkv_w  = (const float*)d_in[1];
    const float* qkv_b  = (const float*)d_in[2];
    const float* proj_w = (const float*)d_in[3];
    const float* proj_b = (const float*)d_in[4];
    const float* rpd    = (const float*)d_in[5];
    const float* rph    = (const float*)d_in[6];
    const float* rpw    = (const float*)d_in[7];
    float* out = (float*)d_out;

    cudaFuncSetAttribute(flash_kernel,
                         cudaFuncAttributeMaxDynamicSharedMemorySize, FL_BYTES);

    prep_round<<<1184, 256>>>(x, qkv_w, proj_w);
    mm_tf32<0><<<dim3(32, 18), 256>>>(qkv_b, nullptr);
    flash_kernel<<<dim3(16, NHB), 256, FL_BYTES>>>(rpd, rph, rpw);
    mm_tf32<1><<<dim3(32, 6), 256>>>(proj_b, out);
}